// round 6
// baseline (speedup 1.0000x reference)
#include <cuda_runtime.h>
#include <math.h>

// Problem constants (fixed by setup_inputs)
#define NN   50000
#define EE   800000
#define EP   850000      // EE + NN self loops
#define FIN  128
#define H1   4
#define HID  64
#define HC   256         // H1*HID
#define NC   10
#define NEG_SLOPE 0.2f
#define SCAN_B 512
#define NBLK  ((NN + SCAN_B - 1) / SCAN_B)   // 98

// ---------------- scratch (device globals; no runtime allocation) ----------
static __device__ __align__(16) float g_h1[(size_t)NN * HC];   // 51.2 MB
static __device__ __align__(16) float g_as1[NN * H1];
static __device__ __align__(16) float g_ad1[NN * H1];
static __device__ __align__(16) float g_h2[NN * NC];
static __device__ __align__(16) float g_as2[NN];
static __device__ __align__(16) float g_ad2[NN];
// CSR (dst-sorted adjacency; rebuilt every call)
static __device__ int g_deg[NN];
static __device__ int g_off[NN + 1];
static __device__ int g_pos[NN];
static __device__ int g_adj[EP];     // source node per CSR slot
static __device__ int g_bsum[NBLK];
static __device__ int g_bbase[NBLK];

// ---------------- helpers ----------------
__device__ __forceinline__ float lrelu(float x) {
    return (x > 0.f) ? x : NEG_SLOPE * x;
}
__device__ __forceinline__ int clampN(int v) {
    return v < 0 ? 0 : (v >= NN ? NN - 1 : v);
}

// ---------------- GEMM1: h1 = x @ W1  [NN,128]x[128,256], 128x128x8 -------
__global__ __launch_bounds__(256) void k_gemm1(const float* __restrict__ X,
                                               const float* __restrict__ W) {
    __shared__ float As[8][132];
    __shared__ float Bs[8][128];
    const int t  = threadIdx.x;
    const int m0 = blockIdx.y * 128;
    const int n0 = blockIdx.x * 128;
    const int ty = t >> 4;         // 0..15 -> rows ty*8..
    const int tx = t & 15;         // 0..15 -> cols tx*8..
    const int ar  = t >> 1;        // 0..127 A row
    const int akq = t & 1;         // k-quad
    const int bk  = t >> 5;        // 0..7 B k-row
    const int bc4 = t & 31;        // B col quad

    float acc[8][8];
#pragma unroll
    for (int i = 0; i < 8; i++)
#pragma unroll
        for (int j = 0; j < 8; j++) acc[i][j] = 0.f;

    for (int k0 = 0; k0 < FIN; k0 += 8) {
        const int gr = m0 + ar;
        float4 a4 = make_float4(0.f, 0.f, 0.f, 0.f);
        if (gr < NN)
            a4 = *(const float4*)(X + (size_t)gr * FIN + k0 + akq * 4);
        As[akq * 4 + 0][ar] = a4.x;
        As[akq * 4 + 1][ar] = a4.y;
        As[akq * 4 + 2][ar] = a4.z;
        As[akq * 4 + 3][ar] = a4.w;

        float4 b4 = *(const float4*)(W + (size_t)(k0 + bk) * HC + n0 + bc4 * 4);
        *(float4*)&Bs[bk][bc4 * 4] = b4;
        __syncthreads();

#pragma unroll
        for (int k = 0; k < 8; k++) {
            float a[8], b[8];
            *(float4*)&a[0] = *(const float4*)&As[k][ty * 8];
            *(float4*)&a[4] = *(const float4*)&As[k][ty * 8 + 4];
            *(float4*)&b[0] = *(const float4*)&Bs[k][tx * 8];
            *(float4*)&b[4] = *(const float4*)&Bs[k][tx * 8 + 4];
#pragma unroll
            for (int i = 0; i < 8; i++)
#pragma unroll
                for (int j = 0; j < 8; j++) acc[i][j] += a[i] * b[j];
        }
        __syncthreads();
    }
#pragma unroll
    for (int i = 0; i < 8; i++) {
        const int gr = m0 + ty * 8 + i;
        if (gr < NN) {
            float* dst = g_h1 + (size_t)gr * HC + n0 + tx * 8;
            *(float4*)dst       = make_float4(acc[i][0], acc[i][1], acc[i][2], acc[i][3]);
            *(float4*)(dst + 4) = make_float4(acc[i][4], acc[i][5], acc[i][6], acc[i][7]);
        }
    }
}

// ---------------- a_src1/a_dst1 ----------------
__global__ __launch_bounds__(256) void k_asad1(const float* __restrict__ att_src,
                                               const float* __restrict__ att_dst) {
    const int idx = blockIdx.x * blockDim.x + threadIdx.x;
    if (idx >= NN * H1) return;
    const int n = idx >> 2;
    const int h = idx & 3;
    const float* hp  = g_h1 + (size_t)n * HC + h * HID;
    const float* asp = att_src + h * HID;
    const float* adp = att_dst + h * HID;
    float ss = 0.f, sd = 0.f;
#pragma unroll
    for (int c4 = 0; c4 < HID / 4; c4++) {
        float4 v = *(const float4*)(hp + c4 * 4);
        float4 a = *(const float4*)(asp + c4 * 4);
        float4 d = *(const float4*)(adp + c4 * 4);
        ss += v.x * a.x + v.y * a.y + v.z * a.z + v.w * a.w;
        sd += v.x * d.x + v.y * d.y + v.z * d.z + v.w * d.w;
    }
    g_as1[idx] = ss;
    g_ad1[idx] = sd;
}

// ---------------- CSR build ----------------
__global__ __launch_bounds__(256) void k_zero_deg() {
    const int i = blockIdx.x * blockDim.x + threadIdx.x;
    if (i < NN) g_deg[i] = 0;
}

__global__ __launch_bounds__(256) void k_hist(const int* __restrict__ edst) {
    const int e = blockIdx.x * blockDim.x + threadIdx.x;
    if (e >= EP) return;
    const int d = (e < EE) ? clampN(edst[e]) : (e - EE);
    atomicAdd(&g_deg[d], 1);
}

// scan phase A: per-block sum of degrees
__global__ __launch_bounds__(SCAN_B) void k_scanA() {
    __shared__ int ws[SCAN_B / 32];
    const int tid  = threadIdx.x;
    const int lane = tid & 31;
    const int wid  = tid >> 5;
    const int idx  = blockIdx.x * SCAN_B + tid;
    int v = (idx < NN) ? g_deg[idx] : 0;
#pragma unroll
    for (int o = 16; o > 0; o >>= 1)
        v += __shfl_xor_sync(0xFFFFFFFFu, v, o);
    if (lane == 0) ws[wid] = v;
    __syncthreads();
    if (tid < SCAN_B / 32) {
        int s = ws[tid];
#pragma unroll
        for (int o = 8; o > 0; o >>= 1)
            s += __shfl_xor_sync(0xFFFFu, s, o);
        if (tid == 0) g_bsum[blockIdx.x] = s;
    }
}

// scan phase B: exclusive scan of NBLK block sums (single small block)
__global__ __launch_bounds__(128) void k_scanB() {
    __shared__ int ws[4];
    const int tid  = threadIdx.x;
    const int lane = tid & 31;
    const int wid  = tid >> 5;
    int v = (tid < NBLK) ? g_bsum[tid] : 0;
    int x = v;
#pragma unroll
    for (int o = 1; o < 32; o <<= 1) {
        int y = __shfl_up_sync(0xFFFFFFFFu, x, o);
        if (lane >= o) x += y;
    }
    if (lane == 31) ws[wid] = x;
    __syncthreads();
    int base = 0;
    for (int w = 0; w < wid; w++) base += ws[w];
    if (tid < NBLK) g_bbase[tid] = base + x - v;   // exclusive
    if (tid == 127) g_off[NN] = base + x;          // total (= EP)
}

// scan phase C: per-block rescan + base, write off/pos
__global__ __launch_bounds__(SCAN_B) void k_scanC() {
    __shared__ int ws[SCAN_B / 32];
    const int tid  = threadIdx.x;
    const int lane = tid & 31;
    const int wid  = tid >> 5;
    const int idx  = blockIdx.x * SCAN_B + tid;
    const int v = (idx < NN) ? g_deg[idx] : 0;
    int x = v;
#pragma unroll
    for (int o = 1; o < 32; o <<= 1) {
        int y = __shfl_up_sync(0xFFFFFFFFu, x, o);
        if (lane >= o) x += y;
    }
    if (lane == 31) ws[wid] = x;
    __syncthreads();
    if (wid == 0 && lane < SCAN_B / 32) {
        int s = ws[lane];
#pragma unroll
        for (int o = 1; o < SCAN_B / 32; o <<= 1) {
            int y = __shfl_up_sync(0xFFFFu, s, o);
            if (lane >= o) s += y;
        }
        ws[lane] = s;
    }
    __syncthreads();
    if (idx < NN) {
        const int excl = g_bbase[blockIdx.x] + (wid ? ws[wid - 1] : 0) + x - v;
        g_off[idx] = excl;
        g_pos[idx] = excl;
    }
}

__global__ __launch_bounds__(256) void k_fill(const int* __restrict__ esrc,
                                              const int* __restrict__ edst) {
    const int e = blockIdx.x * blockDim.x + threadIdx.x;
    if (e >= EP) return;
    int s, d;
    if (e < EE) { s = clampN(esrc[e]); d = clampN(edst[e]); }
    else        { s = d = e - EE; }
    const int p = atomicAdd(&g_pos[d], 1);
    g_adj[p] = s;
}

// ------- layer1: warp-per-dst softmax + aggregation, fused with node2 -----
// lane owns 8 contiguous cols [lane*8, lane*8+8) -> single head (lane>>3),
// two float4 gathers per neighbor, neighbor loop unrolled x2 for MLP.
__global__ __launch_bounds__(256) void k_l1(const float* __restrict__ b1,
                                            const float* __restrict__ W2,
                                            const float* __restrict__ att_src2,
                                            const float* __restrict__ att_dst2) {
    __shared__ int   sh_s[8][32];
    __shared__ float sh_e[8][4][32];   // [warp][head][slot]
    const int warp = threadIdx.x >> 5;
    const int lane = threadIdx.x & 31;
    const int head = lane >> 3;
    const int c0   = lane * 8;
    const int n    = blockIdx.x * 8 + warp;
    if (n >= NN) return;

    const int off = g_off[n];
    const int deg = g_off[n + 1] - off;
    const float4 ad = *(const float4*)(g_ad1 + n * 4);

    // pass 1: per-head max over neighbors
    float4 mx = make_float4(-1e30f, -1e30f, -1e30f, -1e30f);
    for (int i = lane; i < deg; i += 32) {
        const int s = g_adj[off + i];
        const float4 as = *(const float4*)(g_as1 + s * 4);
        mx.x = fmaxf(mx.x, lrelu(as.x + ad.x));
        mx.y = fmaxf(mx.y, lrelu(as.y + ad.y));
        mx.z = fmaxf(mx.z, lrelu(as.z + ad.z));
        mx.w = fmaxf(mx.w, lrelu(as.w + ad.w));
    }
#pragma unroll
    for (int o = 16; o > 0; o >>= 1) {
        mx.x = fmaxf(mx.x, __shfl_xor_sync(0xFFFFFFFFu, mx.x, o));
        mx.y = fmaxf(mx.y, __shfl_xor_sync(0xFFFFFFFFu, mx.y, o));
        mx.z = fmaxf(mx.z, __shfl_xor_sync(0xFFFFFFFFu, mx.z, o));
        mx.w = fmaxf(mx.w, __shfl_xor_sync(0xFFFFFFFFu, mx.w, o));
    }

    // pass 2: chunked exp + unnormalized aggregate
    float4 sum4 = make_float4(0.f, 0.f, 0.f, 0.f);
    float acc[8];
#pragma unroll
    for (int j = 0; j < 8; j++) acc[j] = 0.f;

    for (int base = 0; base < deg; base += 32) {
        const int cnt = min(32, deg - base);
        if (lane < cnt) {
            const int s = g_adj[off + base + lane];
            const float4 as = *(const float4*)(g_as1 + s * 4);
            float4 e4;
            e4.x = expf(lrelu(as.x + ad.x) - mx.x);
            e4.y = expf(lrelu(as.y + ad.y) - mx.y);
            e4.z = expf(lrelu(as.z + ad.z) - mx.z);
            e4.w = expf(lrelu(as.w + ad.w) - mx.w);
            sum4.x += e4.x; sum4.y += e4.y; sum4.z += e4.z; sum4.w += e4.w;
            sh_s[warp][lane]    = s;
            sh_e[warp][0][lane] = e4.x;
            sh_e[warp][1][lane] = e4.y;
            sh_e[warp][2][lane] = e4.z;
            sh_e[warp][3][lane] = e4.w;
        }
        __syncwarp();
        int i = 0;
        for (; i + 2 <= cnt; i += 2) {
            const int s0 = sh_s[warp][i];
            const int s1 = sh_s[warp][i + 1];
            const float e0 = sh_e[warp][head][i];
            const float e1 = sh_e[warp][head][i + 1];
            const float* h0 = g_h1 + (size_t)s0 * HC + c0;
            const float* h1p = g_h1 + (size_t)s1 * HC + c0;
            const float4 a0 = *(const float4*)h0;
            const float4 b0 = *(const float4*)(h0 + 4);
            const float4 a1 = *(const float4*)h1p;
            const float4 b1v = *(const float4*)(h1p + 4);
            acc[0] += e0 * a0.x + e1 * a1.x;
            acc[1] += e0 * a0.y + e1 * a1.y;
            acc[2] += e0 * a0.z + e1 * a1.z;
            acc[3] += e0 * a0.w + e1 * a1.w;
            acc[4] += e0 * b0.x + e1 * b1v.x;
            acc[5] += e0 * b0.y + e1 * b1v.y;
            acc[6] += e0 * b0.z + e1 * b1v.z;
            acc[7] += e0 * b0.w + e1 * b1v.w;
        }
        if (i < cnt) {
            const int s0 = sh_s[warp][i];
            const float e0 = sh_e[warp][head][i];
            const float* h0 = g_h1 + (size_t)s0 * HC + c0;
            const float4 a0 = *(const float4*)h0;
            const float4 b0 = *(const float4*)(h0 + 4);
            acc[0] += e0 * a0.x; acc[1] += e0 * a0.y;
            acc[2] += e0 * a0.z; acc[3] += e0 * a0.w;
            acc[4] += e0 * b0.x; acc[5] += e0 * b0.y;
            acc[6] += e0 * b0.z; acc[7] += e0 * b0.w;
        }
        __syncwarp();
    }
#pragma unroll
    for (int o = 16; o > 0; o >>= 1) {
        sum4.x += __shfl_xor_sync(0xFFFFFFFFu, sum4.x, o);
        sum4.y += __shfl_xor_sync(0xFFFFFFFFu, sum4.y, o);
        sum4.z += __shfl_xor_sync(0xFFFFFFFFu, sum4.z, o);
        sum4.w += __shfl_xor_sync(0xFFFFFFFFu, sum4.w, o);
    }
    const float invv[4] = {1.f / sum4.x, 1.f / sum4.y, 1.f / sum4.z, 1.f / sum4.w};
    const float inv = invv[head];

    // fused node2: bias + ELU, GEMM2 (256->10), att2 dots
    float v[8];
#pragma unroll
    for (int j = 0; j < 8; j++) {
        const float x = acc[j] * inv + b1[c0 + j];
        v[j] = (x > 0.f) ? x : expm1f(x);
    }
    float h2v[NC];
#pragma unroll
    for (int k = 0; k < NC; k++) {
        float p = 0.f;
#pragma unroll
        for (int j = 0; j < 8; j++)
            p += v[j] * W2[(c0 + j) * NC + k];
#pragma unroll
        for (int o = 16; o > 0; o >>= 1)
            p += __shfl_xor_sync(0xFFFFFFFFu, p, o);
        h2v[k] = p;
    }
    if (lane == 0) {
        float s2 = 0.f, d2 = 0.f;
#pragma unroll
        for (int k = 0; k < NC; k++) {
            g_h2[n * NC + k] = h2v[k];
            s2 += h2v[k] * att_src2[k];
            d2 += h2v[k] * att_dst2[k];
        }
        g_as2[n] = s2;
        g_ad2[n] = d2;
    }
}

// ------- layer2: warp-per-dst softmax + aggregation, writes out -----------
__global__ __launch_bounds__(256) void k_l2(const float* __restrict__ b2,
                                            float* __restrict__ out) {
    const int warp = threadIdx.x >> 5;
    const int lane = threadIdx.x & 31;
    const int n    = blockIdx.x * 8 + warp;
    if (n >= NN) return;

    const int off = g_off[n];
    const int deg = g_off[n + 1] - off;
    const float adv = g_ad2[n];

    float mx = -1e30f;
    for (int i = lane; i < deg; i += 32)
        mx = fmaxf(mx, lrelu(g_as2[g_adj[off + i]] + adv));
#pragma unroll
    for (int o = 16; o > 0; o >>= 1)
        mx = fmaxf(mx, __shfl_xor_sync(0xFFFFFFFFu, mx, o));

    float sum = 0.f;
    float acc[NC];
#pragma unroll
    for (int k = 0; k < NC; k++) acc[k] = 0.f;

    for (int i = lane; i < deg; i += 32) {
        const int s = g_adj[off + i];
        const float e = expf(lrelu(g_as2[s] + adv) - mx);
        sum += e;
        const float* hs = g_h2 + s * NC;
#pragma unroll
        for (int k = 0; k < NC; k++) acc[k] += e * hs[k];
    }
#pragma unroll
    for (int o = 16; o > 0; o >>= 1) {
        sum += __shfl_xor_sync(0xFFFFFFFFu, sum, o);
#pragma unroll
        for (int k = 0; k < NC; k++)
            acc[k] += __shfl_xor_sync(0xFFFFFFFFu, acc[k], o);
    }
    if (lane == 0) {
        const float invs = 1.f / sum;
#pragma unroll
        for (int k = 0; k < NC; k++)
            out[n * NC + k] = acc[k] * invs + b2[k];
    }
}

// ---------------- launcher ----------------
extern "C" void kernel_launch(void* const* d_in, const int* in_sizes, int n_in,
                              void* d_out, int out_size) {
    const float* x        = (const float*)d_in[0];
    const int*   ei       = (const int*)d_in[1];   // int32 (JAX x64 disabled)
    const float* W1       = (const float*)d_in[2];
    const float* att_src1 = (const float*)d_in[3];
    const float* att_dst1 = (const float*)d_in[4];
    const float* b1       = (const float*)d_in[5];
    const float* W2       = (const float*)d_in[6];
    const float* att_src2 = (const float*)d_in[7];
    const float* att_dst2 = (const float*)d_in[8];
    const float* b2       = (const float*)d_in[9];
    float*       out      = (float*)d_out;

    const int* esrc = ei;
    const int* edst = ei + EE;

    // CSR build
    k_zero_deg<<<(NN + 255) / 256, 256>>>();
    k_hist<<<(EP + 255) / 256, 256>>>(edst);
    k_scanA<<<NBLK, SCAN_B>>>();
    k_scanB<<<1, 128>>>();
    k_scanC<<<NBLK, SCAN_B>>>();
    k_fill<<<(EP + 255) / 256, 256>>>(esrc, edst);

    // GEMM1 + attention precompute
    {
        dim3 grid(HC / 128, (NN + 127) / 128);
        k_gemm1<<<grid, 256>>>(x, W1);
    }
    k_asad1<<<(NN * H1 + 255) / 256, 256>>>(att_src1, att_dst1);

    // layer1 (softmax+agg+node2 fused)
    k_l1<<<(NN + 7) / 8, 256>>>(b1, W2, att_src2, att_dst2);

    // layer2 (softmax+agg+bias fused, writes out)
    k_l2<<<(NN + 7) / 8, 256>>>(b2, out);
}

// round 7
// speedup vs baseline: 1.3520x; 1.3520x over previous
#include <cuda_runtime.h>
#include <math.h>

// Problem constants (fixed by setup_inputs)
#define NN   50000
#define EE   800000
#define EP   850000      // EE + NN self loops
#define FIN  128
#define H1   4
#define HID  64
#define HC   256         // H1*HID
#define NC   10
#define NEG_SLOPE 0.2f
#define SCAN_B 512
#define NBLK  ((NN + SCAN_B - 1) / SCAN_B)   // 98

// ---------------- scratch (device globals; no runtime allocation) ----------
static __device__ __align__(16) float g_h1[(size_t)NN * HC];   // 51.2 MB
static __device__ __align__(16) float g_as1[NN * H1];
static __device__ __align__(16) float g_ad1[NN * H1];
static __device__ __align__(16) float g_h2[NN * NC];
static __device__ __align__(16) float g_as2[NN];
static __device__ __align__(16) float g_ad2[NN];
// CSR (dst-sorted adjacency; rebuilt every call)
static __device__ int g_deg[NN];
static __device__ int g_off[NN + 1];
static __device__ int g_pos[NN];
static __device__ int g_adj[EP];     // source node per CSR slot
static __device__ int g_bsum[NBLK];
static __device__ int g_bbase[NBLK];

// ---------------- helpers ----------------
__device__ __forceinline__ float lrelu(float x) {
    return (x > 0.f) ? x : NEG_SLOPE * x;
}
__device__ __forceinline__ int clampN(int v) {
    return v < 0 ? 0 : (v >= NN ? NN - 1 : v);
}

// ---------------- GEMM1: h1 = x @ W1  [NN,128]x[128,256], 128x128x8 -------
__global__ __launch_bounds__(256) void k_gemm1(const float* __restrict__ X,
                                               const float* __restrict__ W) {
    __shared__ float As[8][132];
    __shared__ float Bs[8][128];
    const int t  = threadIdx.x;
    const int m0 = blockIdx.y * 128;
    const int n0 = blockIdx.x * 128;
    const int ty = t >> 4;         // 0..15 -> rows ty*8..
    const int tx = t & 15;         // 0..15 -> cols tx*8..
    const int ar  = t >> 1;        // 0..127 A row
    const int akq = t & 1;         // k-quad
    const int bk  = t >> 5;        // 0..7 B k-row
    const int bc4 = t & 31;        // B col quad

    float acc[8][8];
#pragma unroll
    for (int i = 0; i < 8; i++)
#pragma unroll
        for (int j = 0; j < 8; j++) acc[i][j] = 0.f;

    for (int k0 = 0; k0 < FIN; k0 += 8) {
        const int gr = m0 + ar;
        float4 a4 = make_float4(0.f, 0.f, 0.f, 0.f);
        if (gr < NN)
            a4 = *(const float4*)(X + (size_t)gr * FIN + k0 + akq * 4);
        As[akq * 4 + 0][ar] = a4.x;
        As[akq * 4 + 1][ar] = a4.y;
        As[akq * 4 + 2][ar] = a4.z;
        As[akq * 4 + 3][ar] = a4.w;

        float4 b4 = *(const float4*)(W + (size_t)(k0 + bk) * HC + n0 + bc4 * 4);
        *(float4*)&Bs[bk][bc4 * 4] = b4;
        __syncthreads();

#pragma unroll
        for (int k = 0; k < 8; k++) {
            float a[8], b[8];
            *(float4*)&a[0] = *(const float4*)&As[k][ty * 8];
            *(float4*)&a[4] = *(const float4*)&As[k][ty * 8 + 4];
            *(float4*)&b[0] = *(const float4*)&Bs[k][tx * 8];
            *(float4*)&b[4] = *(const float4*)&Bs[k][tx * 8 + 4];
#pragma unroll
            for (int i = 0; i < 8; i++)
#pragma unroll
                for (int j = 0; j < 8; j++) acc[i][j] += a[i] * b[j];
        }
        __syncthreads();
    }
#pragma unroll
    for (int i = 0; i < 8; i++) {
        const int gr = m0 + ty * 8 + i;
        if (gr < NN) {
            float* dst = g_h1 + (size_t)gr * HC + n0 + tx * 8;
            *(float4*)dst       = make_float4(acc[i][0], acc[i][1], acc[i][2], acc[i][3]);
            *(float4*)(dst + 4) = make_float4(acc[i][4], acc[i][5], acc[i][6], acc[i][7]);
        }
    }
}

// ---------------- a_src1/a_dst1 ----------------
__global__ __launch_bounds__(256) void k_asad1(const float* __restrict__ att_src,
                                               const float* __restrict__ att_dst) {
    const int idx = blockIdx.x * blockDim.x + threadIdx.x;
    if (idx >= NN * H1) return;
    const int n = idx >> 2;
    const int h = idx & 3;
    const float* hp  = g_h1 + (size_t)n * HC + h * HID;
    const float* asp = att_src + h * HID;
    const float* adp = att_dst + h * HID;
    float ss = 0.f, sd = 0.f;
#pragma unroll
    for (int c4 = 0; c4 < HID / 4; c4++) {
        float4 v = *(const float4*)(hp + c4 * 4);
        float4 a = *(const float4*)(asp + c4 * 4);
        float4 d = *(const float4*)(adp + c4 * 4);
        ss += v.x * a.x + v.y * a.y + v.z * a.z + v.w * a.w;
        sd += v.x * d.x + v.y * d.y + v.z * d.z + v.w * d.w;
    }
    g_as1[idx] = ss;
    g_ad1[idx] = sd;
}

// ---------------- CSR build ----------------
__global__ __launch_bounds__(256) void k_zero_deg() {
    const int i = blockIdx.x * blockDim.x + threadIdx.x;
    if (i < NN) g_deg[i] = 0;
}

__global__ __launch_bounds__(256) void k_hist(const int* __restrict__ edst) {
    const int e = blockIdx.x * blockDim.x + threadIdx.x;
    if (e >= EP) return;
    const int d = (e < EE) ? clampN(edst[e]) : (e - EE);
    atomicAdd(&g_deg[d], 1);
}

// scan phase A: per-block sum of degrees
__global__ __launch_bounds__(SCAN_B) void k_scanA() {
    __shared__ int ws[SCAN_B / 32];
    const int tid  = threadIdx.x;
    const int lane = tid & 31;
    const int wid  = tid >> 5;
    const int idx  = blockIdx.x * SCAN_B + tid;
    int v = (idx < NN) ? g_deg[idx] : 0;
#pragma unroll
    for (int o = 16; o > 0; o >>= 1)
        v += __shfl_xor_sync(0xFFFFFFFFu, v, o);
    if (lane == 0) ws[wid] = v;
    __syncthreads();
    if (tid < SCAN_B / 32) {
        int s = ws[tid];
#pragma unroll
        for (int o = 8; o > 0; o >>= 1)
            s += __shfl_xor_sync(0xFFFFu, s, o);
        if (tid == 0) g_bsum[blockIdx.x] = s;
    }
}

// scan phase B: exclusive scan of NBLK block sums (single small block)
__global__ __launch_bounds__(128) void k_scanB() {
    __shared__ int ws[4];
    const int tid  = threadIdx.x;
    const int lane = tid & 31;
    const int wid  = tid >> 5;
    int v = (tid < NBLK) ? g_bsum[tid] : 0;
    int x = v;
#pragma unroll
    for (int o = 1; o < 32; o <<= 1) {
        int y = __shfl_up_sync(0xFFFFFFFFu, x, o);
        if (lane >= o) x += y;
    }
    if (lane == 31) ws[wid] = x;
    __syncthreads();
    int base = 0;
    for (int w = 0; w < wid; w++) base += ws[w];
    if (tid < NBLK) g_bbase[tid] = base + x - v;   // exclusive
    if (tid == 127) g_off[NN] = base + x;          // total (= EP)
}

// scan phase C: per-block rescan + base, write off/pos
__global__ __launch_bounds__(SCAN_B) void k_scanC() {
    __shared__ int ws[SCAN_B / 32];
    const int tid  = threadIdx.x;
    const int lane = tid & 31;
    const int wid  = tid >> 5;
    const int idx  = blockIdx.x * SCAN_B + tid;
    const int v = (idx < NN) ? g_deg[idx] : 0;
    int x = v;
#pragma unroll
    for (int o = 1; o < 32; o <<= 1) {
        int y = __shfl_up_sync(0xFFFFFFFFu, x, o);
        if (lane >= o) x += y;
    }
    if (lane == 31) ws[wid] = x;
    __syncthreads();
    if (wid == 0 && lane < SCAN_B / 32) {
        int s = ws[lane];
#pragma unroll
        for (int o = 1; o < SCAN_B / 32; o <<= 1) {
            int y = __shfl_up_sync(0xFFFFu, s, o);
            if (lane >= o) s += y;
        }
        ws[lane] = s;
    }
    __syncthreads();
    if (idx < NN) {
        const int excl = g_bbase[blockIdx.x] + (wid ? ws[wid - 1] : 0) + x - v;
        g_off[idx] = excl;
        g_pos[idx] = excl;
    }
}

__global__ __launch_bounds__(256) void k_fill(const int* __restrict__ esrc,
                                              const int* __restrict__ edst) {
    const int e = blockIdx.x * blockDim.x + threadIdx.x;
    if (e >= EP) return;
    int s, d;
    if (e < EE) { s = clampN(esrc[e]); d = clampN(edst[e]); }
    else        { s = d = e - EE; }
    const int p = atomicAdd(&g_pos[d], 1);
    g_adj[p] = s;
}

// ------- layer1: warp-per-dst softmax + aggregation, fused with node2 -----
// lane owns cols [lane*4, lane*4+4) (heads 0/1) and [128+lane*4, ...) (heads
// 2/3): per neighbor, two warp-contiguous LDG.128 (4 lines each, coalesced),
// unrolled x2 for MLP.
__global__ __launch_bounds__(256) void k_l1(const float* __restrict__ b1,
                                            const float* __restrict__ W2,
                                            const float* __restrict__ att_src2,
                                            const float* __restrict__ att_dst2) {
    __shared__ int    sh_s[8][32];
    __shared__ float4 sh_e[8][32];
    const int warp = threadIdx.x >> 5;
    const int lane = threadIdx.x & 31;
    const bool lo  = (lane < 16);
    const int c0   = lane * 4;
    const int n    = blockIdx.x * 8 + warp;
    if (n >= NN) return;

    const int off = g_off[n];
    const int deg = g_off[n + 1] - off;
    const float4 ad = *(const float4*)(g_ad1 + n * 4);

    // pass 1: per-head max over neighbors
    float4 mx = make_float4(-1e30f, -1e30f, -1e30f, -1e30f);
    for (int i = lane; i < deg; i += 32) {
        const int s = g_adj[off + i];
        const float4 as = *(const float4*)(g_as1 + s * 4);
        mx.x = fmaxf(mx.x, lrelu(as.x + ad.x));
        mx.y = fmaxf(mx.y, lrelu(as.y + ad.y));
        mx.z = fmaxf(mx.z, lrelu(as.z + ad.z));
        mx.w = fmaxf(mx.w, lrelu(as.w + ad.w));
    }
#pragma unroll
    for (int o = 16; o > 0; o >>= 1) {
        mx.x = fmaxf(mx.x, __shfl_xor_sync(0xFFFFFFFFu, mx.x, o));
        mx.y = fmaxf(mx.y, __shfl_xor_sync(0xFFFFFFFFu, mx.y, o));
        mx.z = fmaxf(mx.z, __shfl_xor_sync(0xFFFFFFFFu, mx.z, o));
        mx.w = fmaxf(mx.w, __shfl_xor_sync(0xFFFFFFFFu, mx.w, o));
    }

    // pass 2: chunked exp + unnormalized aggregate
    float4 sum4 = make_float4(0.f, 0.f, 0.f, 0.f);
    float4 accA = make_float4(0.f, 0.f, 0.f, 0.f);   // cols c0..c0+3
    float4 accB = make_float4(0.f, 0.f, 0.f, 0.f);   // cols 128+c0..

    for (int base = 0; base < deg; base += 32) {
        const int cnt = min(32, deg - base);
        if (lane < cnt) {
            const int s = g_adj[off + base + lane];
            const float4 as = *(const float4*)(g_as1 + s * 4);
            float4 e4;
            e4.x = expf(lrelu(as.x + ad.x) - mx.x);
            e4.y = expf(lrelu(as.y + ad.y) - mx.y);
            e4.z = expf(lrelu(as.z + ad.z) - mx.z);
            e4.w = expf(lrelu(as.w + ad.w) - mx.w);
            sum4.x += e4.x; sum4.y += e4.y; sum4.z += e4.z; sum4.w += e4.w;
            sh_s[warp][lane] = s;
            sh_e[warp][lane] = e4;
        }
        __syncwarp();
        int i = 0;
        for (; i + 2 <= cnt; i += 2) {
            const int s0 = sh_s[warp][i];
            const int s1 = sh_s[warp][i + 1];
            const float4 e0 = sh_e[warp][i];
            const float4 e1 = sh_e[warp][i + 1];
            const float* h0 = g_h1 + (size_t)s0 * HC;
            const float* h1 = g_h1 + (size_t)s1 * HC;
            const float4 x0 = *(const float4*)(h0 + c0);
            const float4 y0 = *(const float4*)(h0 + 128 + c0);
            const float4 x1 = *(const float4*)(h1 + c0);
            const float4 y1 = *(const float4*)(h1 + 128 + c0);
            const float a0 = lo ? e0.x : e0.y;
            const float b0 = lo ? e0.z : e0.w;
            const float a1 = lo ? e1.x : e1.y;
            const float b1v = lo ? e1.z : e1.w;
            accA.x += a0 * x0.x + a1 * x1.x;
            accA.y += a0 * x0.y + a1 * x1.y;
            accA.z += a0 * x0.z + a1 * x1.z;
            accA.w += a0 * x0.w + a1 * x1.w;
            accB.x += b0 * y0.x + b1v * y1.x;
            accB.y += b0 * y0.y + b1v * y1.y;
            accB.z += b0 * y0.z + b1v * y1.z;
            accB.w += b0 * y0.w + b1v * y1.w;
        }
        if (i < cnt) {
            const int s0 = sh_s[warp][i];
            const float4 e0 = sh_e[warp][i];
            const float* h0 = g_h1 + (size_t)s0 * HC;
            const float4 x0 = *(const float4*)(h0 + c0);
            const float4 y0 = *(const float4*)(h0 + 128 + c0);
            const float a0 = lo ? e0.x : e0.y;
            const float b0 = lo ? e0.z : e0.w;
            accA.x += a0 * x0.x; accA.y += a0 * x0.y;
            accA.z += a0 * x0.z; accA.w += a0 * x0.w;
            accB.x += b0 * y0.x; accB.y += b0 * y0.y;
            accB.z += b0 * y0.z; accB.w += b0 * y0.w;
        }
        __syncwarp();
    }
#pragma unroll
    for (int o = 16; o > 0; o >>= 1) {
        sum4.x += __shfl_xor_sync(0xFFFFFFFFu, sum4.x, o);
        sum4.y += __shfl_xor_sync(0xFFFFFFFFu, sum4.y, o);
        sum4.z += __shfl_xor_sync(0xFFFFFFFFu, sum4.z, o);
        sum4.w += __shfl_xor_sync(0xFFFFFFFFu, sum4.w, o);
    }
    const float invA = lo ? (1.f / sum4.x) : (1.f / sum4.y);
    const float invB = lo ? (1.f / sum4.z) : (1.f / sum4.w);

    // fused node2: bias + ELU, GEMM2 (256->10), att2 dots
    // lane's 8 cols: c0..c0+3 and 128+c0..128+c0+3
    float v[8];
    {
        const float4 bA = *(const float4*)(b1 + c0);
        const float4 bB = *(const float4*)(b1 + 128 + c0);
        const float t0 = accA.x * invA + bA.x;
        const float t1 = accA.y * invA + bA.y;
        const float t2 = accA.z * invA + bA.z;
        const float t3 = accA.w * invA + bA.w;
        const float t4 = accB.x * invB + bB.x;
        const float t5 = accB.y * invB + bB.y;
        const float t6 = accB.z * invB + bB.z;
        const float t7 = accB.w * invB + bB.w;
        v[0] = (t0 > 0.f) ? t0 : expm1f(t0);
        v[1] = (t1 > 0.f) ? t1 : expm1f(t1);
        v[2] = (t2 > 0.f) ? t2 : expm1f(t2);
        v[3] = (t3 > 0.f) ? t3 : expm1f(t3);
        v[4] = (t4 > 0.f) ? t4 : expm1f(t4);
        v[5] = (t5 > 0.f) ? t5 : expm1f(t5);
        v[6] = (t6 > 0.f) ? t6 : expm1f(t6);
        v[7] = (t7 > 0.f) ? t7 : expm1f(t7);
    }
    float h2v[NC];
#pragma unroll
    for (int k = 0; k < NC; k++) {
        float p = 0.f;
#pragma unroll
        for (int j = 0; j < 4; j++)
            p += v[j] * W2[(c0 + j) * NC + k];
#pragma unroll
        for (int j = 0; j < 4; j++)
            p += v[4 + j] * W2[(128 + c0 + j) * NC + k];
#pragma unroll
        for (int o = 16; o > 0; o >>= 1)
            p += __shfl_xor_sync(0xFFFFFFFFu, p, o);
        h2v[k] = p;
    }
    if (lane == 0) {
        float s2 = 0.f, d2 = 0.f;
#pragma unroll
        for (int k = 0; k < NC; k++) {
            g_h2[n * NC + k] = h2v[k];
            s2 += h2v[k] * att_src2[k];
            d2 += h2v[k] * att_dst2[k];
        }
        g_as2[n] = s2;
        g_ad2[n] = d2;
    }
}

// ------- layer2: warp-per-dst softmax + aggregation, writes out -----------
__global__ __launch_bounds__(256) void k_l2(const float* __restrict__ b2,
                                            float* __restrict__ out) {
    const int warp = threadIdx.x >> 5;
    const int lane = threadIdx.x & 31;
    const int n    = blockIdx.x * 8 + warp;
    if (n >= NN) return;

    const int off = g_off[n];
    const int deg = g_off[n + 1] - off;
    const float adv = g_ad2[n];

    float mx = -1e30f;
    for (int i = lane; i < deg; i += 32)
        mx = fmaxf(mx, lrelu(g_as2[g_adj[off + i]] + adv));
#pragma unroll
    for (int o = 16; o > 0; o >>= 1)
        mx = fmaxf(mx, __shfl_xor_sync(0xFFFFFFFFu, mx, o));

    float sum = 0.f;
    float acc[NC];
#pragma unroll
    for (int k = 0; k < NC; k++) acc[k] = 0.f;

    for (int i = lane; i < deg; i += 32) {
        const int s = g_adj[off + i];
        const float e = expf(lrelu(g_as2[s] + adv) - mx);
        sum += e;
        const float* hs = g_h2 + s * NC;
#pragma unroll
        for (int k = 0; k < NC; k++) acc[k] += e * hs[k];
    }
#pragma unroll
    for (int o = 16; o > 0; o >>= 1) {
        sum += __shfl_xor_sync(0xFFFFFFFFu, sum, o);
#pragma unroll
        for (int k = 0; k < NC; k++)
            acc[k] += __shfl_xor_sync(0xFFFFFFFFu, acc[k], o);
    }
    if (lane == 0) {
        const float invs = 1.f / sum;
#pragma unroll
        for (int k = 0; k < NC; k++)
            out[n * NC + k] = acc[k] * invs + b2[k];
    }
}

// ---------------- launcher ----------------
extern "C" void kernel_launch(void* const* d_in, const int* in_sizes, int n_in,
                              void* d_out, int out_size) {
    const float* x        = (const float*)d_in[0];
    const int*   ei       = (const int*)d_in[1];   // int32 (JAX x64 disabled)
    const float* W1       = (const float*)d_in[2];
    const float* att_src1 = (const float*)d_in[3];
    const float* att_dst1 = (const float*)d_in[4];
    const float* b1       = (const float*)d_in[5];
    const float* W2       = (const float*)d_in[6];
    const float* att_src2 = (const float*)d_in[7];
    const float* att_dst2 = (const float*)d_in[8];
    const float* b2       = (const float*)d_in[9];
    float*       out      = (float*)d_out;

    const int* esrc = ei;
    const int* edst = ei + EE;

    // CSR build
    k_zero_deg<<<(NN + 255) / 256, 256>>>();
    k_hist<<<(EP + 255) / 256, 256>>>(edst);
    k_scanA<<<NBLK, SCAN_B>>>();
    k_scanB<<<1, 128>>>();
    k_scanC<<<NBLK, SCAN_B>>>();
    k_fill<<<(EP + 255) / 256, 256>>>(esrc, edst);

    // GEMM1 + attention precompute
    {
        dim3 grid(HC / 128, (NN + 127) / 128);
        k_gemm1<<<grid, 256>>>(x, W1);
    }
    k_asad1<<<(NN * H1 + 255) / 256, 256>>>(att_src1, att_dst1);

    // layer1 (softmax+agg+node2 fused)
    k_l1<<<(NN + 7) / 8, 256>>>(b1, W2, att_src2, att_dst2);

    // layer2 (softmax+agg+bias fused, writes out)
    k_l2<<<(NN + 7) / 8, 256>>>(b2, out);
}

// round 9
// speedup vs baseline: 1.7380x; 1.2855x over previous
#include <cuda_runtime.h>
#include <math.h>

// Problem constants (fixed by setup_inputs)
#define NN   50000
#define EE   800000
#define EP   850000      // EE + NN self loops
#define FIN  128
#define H1   4
#define HID  64
#define HC   256         // H1*HID
#define NC   10
#define NEG_SLOPE 0.2f
#define SCAN_B 512
#define NBLK  ((NN + SCAN_B - 1) / SCAN_B)   // 98

// ---------------- scratch (device globals; no runtime allocation) ----------
static __device__ __align__(16) float g_h1[(size_t)NN * HC];   // 51.2 MB
static __device__ __align__(16) float g_as1[NN * H1];
static __device__ __align__(16) float g_ad1[NN * H1];
static __device__ __align__(16) float g_h2[NN * NC];
static __device__ __align__(16) float g_as2[NN];
static __device__ __align__(16) float g_ad2[NN];
// CSR (dst-sorted adjacency; rebuilt every call)
static __device__ int g_deg[NN];
static __device__ int g_off[NN + 1];
static __device__ int g_pos[NN];
static __device__ int g_adj[EP];     // source node per CSR slot
static __device__ int g_bsum[NBLK];
static __device__ int g_bbase[NBLK];

// ---------------- helpers ----------------
__device__ __forceinline__ float lrelu(float x) {
    return (x > 0.f) ? x : NEG_SLOPE * x;
}
__device__ __forceinline__ int clampN(int v) {
    return v < 0 ? 0 : (v >= NN ? NN - 1 : v);
}
__device__ __forceinline__ unsigned int f2tf32(float x) {
    unsigned int r;
    asm("cvt.rna.tf32.f32 %0, %1;" : "=r"(r) : "f"(x));
    return r;
}
__device__ __forceinline__ void mma_tf32(float* d, const unsigned int* a,
                                         const unsigned int* b) {
    asm volatile(
        "mma.sync.aligned.m16n8k8.row.col.f32.tf32.tf32.f32 "
        "{%0,%1,%2,%3},{%4,%5,%6,%7},{%8,%9},{%0,%1,%2,%3};"
        : "+f"(d[0]), "+f"(d[1]), "+f"(d[2]), "+f"(d[3])
        : "r"(a[0]), "r"(a[1]), "r"(a[2]), "r"(a[3]), "r"(b[0]), "r"(b[1]));
}

// ---- GEMM1: h1 = x @ W1 [NN,128]x[128,256], tf32 tensor cores, 3x split --
#define GBM 128
#define GBN 128
#define GBK 32
#define GPAD 8   // row padding: (k*136+c) banks = 8k+c mod 32 -> conflict-free

__global__ __launch_bounds__(256, 1) void k_gemm1(const float* __restrict__ X,
                                                  const float* __restrict__ W) {
    __shared__ float As[GBK][GBM + GPAD];   // [k][m]
    __shared__ float Bs[GBK][GBN + GPAD];   // [k][n]
    const int t    = threadIdx.x;
    const int warp = t >> 5;
    const int lane = t & 31;
    const int g    = lane >> 2;    // group 0..7
    const int tg   = lane & 3;     // thread-in-group 0..3
    const int wm   = (warp >> 1) * 32;   // warp row offset in block tile
    const int wn   = (warp & 1) * 64;    // warp col offset
    const int m0   = blockIdx.y * GBM;
    const int n0   = blockIdx.x * GBN;

    float d[2][8][4];
#pragma unroll
    for (int mt = 0; mt < 2; mt++)
#pragma unroll
        for (int nt = 0; nt < 8; nt++)
#pragma unroll
            for (int i = 0; i < 4; i++) d[mt][nt][i] = 0.f;

    for (int k0 = 0; k0 < FIN; k0 += GBK) {
        // A: X[m][k] -> As[k][m] (transpose on store)
#pragma unroll
        for (int it = 0; it < 4; it++) {
            const int idx = it * 256 + t;
            const int row = idx >> 3;        // 0..127
            const int kq  = idx & 7;         // 0..7 (float4 along k)
            const int gr  = m0 + row;
            float4 v = make_float4(0.f, 0.f, 0.f, 0.f);
            if (gr < NN)
                v = *(const float4*)(X + (size_t)gr * FIN + k0 + kq * 4);
            As[kq * 4 + 0][row] = v.x;
            As[kq * 4 + 1][row] = v.y;
            As[kq * 4 + 2][row] = v.z;
            As[kq * 4 + 3][row] = v.w;
        }
        // B: W[k][n] -> Bs[k][n] (direct, coalesced)
#pragma unroll
        for (int it = 0; it < 4; it++) {
            const int idx  = it * 256 + t;
            const int krow = idx >> 5;       // 0..31
            const int nq   = idx & 31;       // float4 along n
            *(float4*)&Bs[krow][nq * 4] =
                *(const float4*)(W + (size_t)(k0 + krow) * HC + n0 + nq * 4);
        }
        __syncthreads();

#pragma unroll
        for (int ks = 0; ks < 4; ks++) {
            const int kk = ks * 8;
            unsigned int ah[2][4], al[2][4];
#pragma unroll
            for (int mt = 0; mt < 2; mt++) {
                const int mb = wm + mt * 16 + g;
                const float a0 = As[kk + tg][mb];
                const float a1 = As[kk + tg][mb + 8];
                const float a2 = As[kk + tg + 4][mb];
                const float a3 = As[kk + tg + 4][mb + 8];
                ah[mt][0] = f2tf32(a0); al[mt][0] = f2tf32(a0 - __uint_as_float(ah[mt][0]));
                ah[mt][1] = f2tf32(a1); al[mt][1] = f2tf32(a1 - __uint_as_float(ah[mt][1]));
                ah[mt][2] = f2tf32(a2); al[mt][2] = f2tf32(a2 - __uint_as_float(ah[mt][2]));
                ah[mt][3] = f2tf32(a3); al[mt][3] = f2tf32(a3 - __uint_as_float(ah[mt][3]));
            }
            unsigned int bh[8][2], bl[8][2];
#pragma unroll
            for (int nt = 0; nt < 8; nt++) {
                const int nb = wn + nt * 8 + g;
                const float b0 = Bs[kk + tg][nb];
                const float b1 = Bs[kk + tg + 4][nb];
                bh[nt][0] = f2tf32(b0); bl[nt][0] = f2tf32(b0 - __uint_as_float(bh[nt][0]));
                bh[nt][1] = f2tf32(b1); bl[nt][1] = f2tf32(b1 - __uint_as_float(bh[nt][1]));
            }
#pragma unroll
            for (int mt = 0; mt < 2; mt++)
#pragma unroll
                for (int nt = 0; nt < 8; nt++) {
                    mma_tf32(d[mt][nt], ah[mt], bh[nt]);
                    mma_tf32(d[mt][nt], ah[mt], bl[nt]);
                    mma_tf32(d[mt][nt], al[mt], bh[nt]);
                }
        }
        __syncthreads();
    }

    // store D
#pragma unroll
    for (int mt = 0; mt < 2; mt++) {
        const int r0 = m0 + wm + mt * 16 + g;
        const int r1 = r0 + 8;
#pragma unroll
        for (int nt = 0; nt < 8; nt++) {
            const int col = n0 + wn + nt * 8 + tg * 2;
            if (r0 < NN)
                *(float2*)(g_h1 + (size_t)r0 * HC + col) =
                    make_float2(d[mt][nt][0], d[mt][nt][1]);
            if (r1 < NN)
                *(float2*)(g_h1 + (size_t)r1 * HC + col) =
                    make_float2(d[mt][nt][2], d[mt][nt][3]);
        }
    }
}

// ---------------- a_src1/a_dst1 ----------------
__global__ __launch_bounds__(256) void k_asad1(const float* __restrict__ att_src,
                                               const float* __restrict__ att_dst) {
    const int idx = blockIdx.x * blockDim.x + threadIdx.x;
    if (idx >= NN * H1) return;
    const int n = idx >> 2;
    const int h = idx & 3;
    const float* hp  = g_h1 + (size_t)n * HC + h * HID;
    const float* asp = att_src + h * HID;
    const float* adp = att_dst + h * HID;
    float ss = 0.f, sd = 0.f;
#pragma unroll
    for (int c4 = 0; c4 < HID / 4; c4++) {
        float4 v = *(const float4*)(hp + c4 * 4);
        float4 a = *(const float4*)(asp + c4 * 4);
        float4 d = *(const float4*)(adp + c4 * 4);
        ss += v.x * a.x + v.y * a.y + v.z * a.z + v.w * a.w;
        sd += v.x * d.x + v.y * d.y + v.z * d.z + v.w * d.w;
    }
    g_as1[idx] = ss;
    g_ad1[idx] = sd;
}

// ---------------- CSR build ----------------
__global__ __launch_bounds__(256) void k_zero_deg() {
    const int i = blockIdx.x * blockDim.x + threadIdx.x;
    if (i < NN) g_deg[i] = 0;
}

__global__ __launch_bounds__(256) void k_hist(const int* __restrict__ edst) {
    const int e = blockIdx.x * blockDim.x + threadIdx.x;
    if (e >= EP) return;
    const int d = (e < EE) ? clampN(edst[e]) : (e - EE);
    atomicAdd(&g_deg[d], 1);
}

// scan phase A: per-block sum of degrees
__global__ __launch_bounds__(SCAN_B) void k_scanA() {
    __shared__ int ws[SCAN_B / 32];
    const int tid  = threadIdx.x;
    const int lane = tid & 31;
    const int wid  = tid >> 5;
    const int idx  = blockIdx.x * SCAN_B + tid;
    int v = (idx < NN) ? g_deg[idx] : 0;
#pragma unroll
    for (int o = 16; o > 0; o >>= 1)
        v += __shfl_xor_sync(0xFFFFFFFFu, v, o);
    if (lane == 0) ws[wid] = v;
    __syncthreads();
    if (tid < SCAN_B / 32) {
        int s = ws[tid];
#pragma unroll
        for (int o = 8; o > 0; o >>= 1)
            s += __shfl_xor_sync(0xFFFFu, s, o);
        if (tid == 0) g_bsum[blockIdx.x] = s;
    }
}

// scan phase B: exclusive scan of NBLK block sums (single small block)
__global__ __launch_bounds__(128) void k_scanB() {
    __shared__ int ws[4];
    const int tid  = threadIdx.x;
    const int lane = tid & 31;
    const int wid  = tid >> 5;
    int v = (tid < NBLK) ? g_bsum[tid] : 0;
    int x = v;
#pragma unroll
    for (int o = 1; o < 32; o <<= 1) {
        int y = __shfl_up_sync(0xFFFFFFFFu, x, o);
        if (lane >= o) x += y;
    }
    if (lane == 31) ws[wid] = x;
    __syncthreads();
    int base = 0;
    for (int w = 0; w < wid; w++) base += ws[w];
    if (tid < NBLK) g_bbase[tid] = base + x - v;   // exclusive
    if (tid == 127) g_off[NN] = base + x;          // total (= EP)
}

// scan phase C: per-block rescan + base, write off/pos
__global__ __launch_bounds__(SCAN_B) void k_scanC() {
    __shared__ int ws[SCAN_B / 32];
    const int tid  = threadIdx.x;
    const int lane = tid & 31;
    const int wid  = tid >> 5;
    const int idx  = blockIdx.x * SCAN_B + tid;
    const int v = (idx < NN) ? g_deg[idx] : 0;
    int x = v;
#pragma unroll
    for (int o = 1; o < 32; o <<= 1) {
        int y = __shfl_up_sync(0xFFFFFFFFu, x, o);
        if (lane >= o) x += y;
    }
    if (lane == 31) ws[wid] = x;
    __syncthreads();
    if (wid == 0 && lane < SCAN_B / 32) {
        int s = ws[lane];
#pragma unroll
        for (int o = 1; o < SCAN_B / 32; o <<= 1) {
            int y = __shfl_up_sync(0xFFFFu, s, o);
            if (lane >= o) s += y;
        }
        ws[lane] = s;
    }
    __syncthreads();
    if (idx < NN) {
        const int excl = g_bbase[blockIdx.x] + (wid ? ws[wid - 1] : 0) + x - v;
        g_off[idx] = excl;
        g_pos[idx] = excl;
    }
}

__global__ __launch_bounds__(256) void k_fill(const int* __restrict__ esrc,
                                              const int* __restrict__ edst) {
    const int e = blockIdx.x * blockDim.x + threadIdx.x;
    if (e >= EP) return;
    int s, d;
    if (e < EE) { s = clampN(esrc[e]); d = clampN(edst[e]); }
    else        { s = d = e - EE; }
    const int p = atomicAdd(&g_pos[d], 1);
    g_adj[p] = s;
}

// ------- layer1: warp-per-dst softmax + aggregation, fused with node2 -----
// (round-5 layout: 8 coalesced scalar LDG per neighbor — optimal per L1tex
//  wavefront model: 8 x 1-line LDG @1.0cyc/wf beats vectorized multi-line)
__global__ __launch_bounds__(256) void k_l1(const float* __restrict__ b1,
                                            const float* __restrict__ W2,
                                            const float* __restrict__ att_src2,
                                            const float* __restrict__ att_dst2) {
    __shared__ int    sh_s[8][32];
    __shared__ float4 sh_e[8][32];
    const int warp = threadIdx.x >> 5;
    const int lane = threadIdx.x & 31;
    const int n    = blockIdx.x * 8 + warp;
    if (n >= NN) return;

    const int off = g_off[n];
    const int deg = g_off[n + 1] - off;
    const float4 ad = *(const float4*)(g_ad1 + n * 4);

    // pass 1: per-head max over neighbors
    float4 mx = make_float4(-1e30f, -1e30f, -1e30f, -1e30f);
    for (int i = lane; i < deg; i += 32) {
        const int s = g_adj[off + i];
        const float4 as = *(const float4*)(g_as1 + s * 4);
        mx.x = fmaxf(mx.x, lrelu(as.x + ad.x));
        mx.y = fmaxf(mx.y, lrelu(as.y + ad.y));
        mx.z = fmaxf(mx.z, lrelu(as.z + ad.z));
        mx.w = fmaxf(mx.w, lrelu(as.w + ad.w));
    }
#pragma unroll
    for (int o = 16; o > 0; o >>= 1) {
        mx.x = fmaxf(mx.x, __shfl_xor_sync(0xFFFFFFFFu, mx.x, o));
        mx.y = fmaxf(mx.y, __shfl_xor_sync(0xFFFFFFFFu, mx.y, o));
        mx.z = fmaxf(mx.z, __shfl_xor_sync(0xFFFFFFFFu, mx.z, o));
        mx.w = fmaxf(mx.w, __shfl_xor_sync(0xFFFFFFFFu, mx.w, o));
    }

    // pass 2: chunked exp + unnormalized aggregate
    float4 sum4 = make_float4(0.f, 0.f, 0.f, 0.f);
    float acc[8];
#pragma unroll
    for (int j = 0; j < 8; j++) acc[j] = 0.f;

    for (int base = 0; base < deg; base += 32) {
        const int cnt = min(32, deg - base);
        if (lane < cnt) {
            const int s = g_adj[off + base + lane];
            const float4 as = *(const float4*)(g_as1 + s * 4);
            float4 e4;
            e4.x = expf(lrelu(as.x + ad.x) - mx.x);
            e4.y = expf(lrelu(as.y + ad.y) - mx.y);
            e4.z = expf(lrelu(as.z + ad.z) - mx.z);
            e4.w = expf(lrelu(as.w + ad.w) - mx.w);
            sum4.x += e4.x; sum4.y += e4.y; sum4.z += e4.z; sum4.w += e4.w;
            sh_s[warp][lane] = s;
            sh_e[warp][lane] = e4;
        }
        __syncwarp();
        for (int i = 0; i < cnt; i++) {
            const int    s  = sh_s[warp][i];
            const float4 e4 = sh_e[warp][i];
            const float* hs = g_h1 + (size_t)s * HC;
            const float ev[4] = {e4.x, e4.y, e4.z, e4.w};
#pragma unroll
            for (int j = 0; j < 8; j++)
                acc[j] += ev[j >> 1] * hs[j * 32 + lane];
        }
        __syncwarp();
    }
#pragma unroll
    for (int o = 16; o > 0; o >>= 1) {
        sum4.x += __shfl_xor_sync(0xFFFFFFFFu, sum4.x, o);
        sum4.y += __shfl_xor_sync(0xFFFFFFFFu, sum4.y, o);
        sum4.z += __shfl_xor_sync(0xFFFFFFFFu, sum4.z, o);
        sum4.w += __shfl_xor_sync(0xFFFFFFFFu, sum4.w, o);
    }
    const float invv[4] = {1.f / sum4.x, 1.f / sum4.y, 1.f / sum4.z, 1.f / sum4.w};

    // fused node2: bias + ELU, GEMM2 (256->10), att2 dots
    float v[8];
#pragma unroll
    for (int j = 0; j < 8; j++) {
        const float x = acc[j] * invv[j >> 1] + b1[j * 32 + lane];
        v[j] = (x > 0.f) ? x : expm1f(x);
    }
    float h2v[NC];
#pragma unroll
    for (int k = 0; k < NC; k++) {
        float p = 0.f;
#pragma unroll
        for (int j = 0; j < 8; j++)
            p += v[j] * W2[(j * 32 + lane) * NC + k];
#pragma unroll
        for (int o = 16; o > 0; o >>= 1)
            p += __shfl_xor_sync(0xFFFFFFFFu, p, o);
        h2v[k] = p;
    }
    if (lane == 0) {
        float s2 = 0.f, d2 = 0.f;
#pragma unroll
        for (int k = 0; k < NC; k++) {
            g_h2[n * NC + k] = h2v[k];
            s2 += h2v[k] * att_src2[k];
            d2 += h2v[k] * att_dst2[k];
        }
        g_as2[n] = s2;
        g_ad2[n] = d2;
    }
}

// ------- layer2: warp-per-dst softmax + aggregation, writes out -----------
__global__ __launch_bounds__(256) void k_l2(const float* __restrict__ b2,
                                            float* __restrict__ out) {
    const int warp = threadIdx.x >> 5;
    const int lane = threadIdx.x & 31;
    const int n    = blockIdx.x * 8 + warp;
    if (n >= NN) return;

    const int off = g_off[n];
    const int deg = g_off[n + 1] - off;
    const float adv = g_ad2[n];

    float mx = -1e30f;
    for (int i = lane; i < deg; i += 32)
        mx = fmaxf(mx, lrelu(g_as2[g_adj[off + i]] + adv));
#pragma unroll
    for (int o = 16; o > 0; o >>= 1)
        mx = fmaxf(mx, __shfl_xor_sync(0xFFFFFFFFu, mx, o));

    float sum = 0.f;
    float acc[NC];
#pragma unroll
    for (int k = 0; k < NC; k++) acc[k] = 0.f;

    for (int i = lane; i < deg; i += 32) {
        const int s = g_adj[off + i];
        const float e = expf(lrelu(g_as2[s] + adv) - mx);
        sum += e;
        const float* hs = g_h2 + s * NC;
#pragma unroll
        for (int k = 0; k < NC; k++) acc[k] += e * hs[k];
    }
#pragma unroll
    for (int o = 16; o > 0; o >>= 1) {
        sum += __shfl_xor_sync(0xFFFFFFFFu, sum, o);
#pragma unroll
        for (int k = 0; k < NC; k++)
            acc[k] += __shfl_xor_sync(0xFFFFFFFFu, acc[k], o);
    }
    if (lane == 0) {
        const float invs = 1.f / sum;
#pragma unroll
        for (int k = 0; k < NC; k++)
            out[n * NC + k] = acc[k] * invs + b2[k];
    }
}

// ---------------- launcher ----------------
extern "C" void kernel_launch(void* const* d_in, const int* in_sizes, int n_in,
                              void* d_out, int out_size) {
    const float* x        = (const float*)d_in[0];
    const int*   ei       = (const int*)d_in[1];   // int32 (JAX x64 disabled)
    const float* W1       = (const float*)d_in[2];
    const float* att_src1 = (const float*)d_in[3];
    const float* att_dst1 = (const float*)d_in[4];
    const float* b1       = (const float*)d_in[5];
    const float* W2       = (const float*)d_in[6];
    const float* att_src2 = (const float*)d_in[7];
    const float* att_dst2 = (const float*)d_in[8];
    const float* b2       = (const float*)d_in[9];
    float*       out      = (float*)d_out;

    const int* esrc = ei;
    const int* edst = ei + EE;

    // CSR build
    k_zero_deg<<<(NN + 255) / 256, 256>>>();
    k_hist<<<(EP + 255) / 256, 256>>>(edst);
    k_scanA<<<NBLK, SCAN_B>>>();
    k_scanB<<<1, 128>>>();
    k_scanC<<<NBLK, SCAN_B>>>();
    k_fill<<<(EP + 255) / 256, 256>>>(esrc, edst);

    // GEMM1 (tf32 tensor cores) + attention precompute
    {
        dim3 grid(HC / GBN, (NN + GBM - 1) / GBM);
        k_gemm1<<<grid, 256>>>(x, W1);
    }
    k_asad1<<<(NN * H1 + 255) / 256, 256>>>(att_src1, att_dst1);

    // layer1 (softmax+agg+node2 fused)
    k_l1<<<(NN + 7) / 8, 256>>>(b1, W2, att_src2, att_dst2);

    // layer2 (softmax+agg+bias fused, writes out)
    k_l2<<<(NN + 7) / 8, 256>>>(b2, out);
}